// round 3
// baseline (speedup 1.0000x reference)
#include <cuda_runtime.h>
#include <math.h>

#define DEVINL __device__ __forceinline__

static DEVINL float leaky(float v){ return v > 0.f ? v : 0.2f*v; }

// ---------------- persistent scratch (no runtime allocation) ----------------
__device__ float g_cc [4*128*64];
__device__ float g_tmp[4*128*64];
__device__ float g_bb [512*512];
__device__ float g_k  [512*98304];            // 201 MB kernel-predictor output
__device__ float g_h  [2][4*32768*64];        // ping-pong h
__device__ float g_o1 [4*32768*64];           // dilated-conv output

// ================= cond input conv (k=5, 80->64) =================
__global__ void k_cond_in(const float* __restrict__ c, const float* __restrict__ w,
                          const float* __restrict__ bias){
  int b = blockIdx.y, l = blockIdx.x, o = threadIdx.x;
  float acc = bias[o];
  #pragma unroll
  for (int t=0;t<5;t++){
    int ls = l - 2 + t;
    if (ls < 0 || ls >= 128) continue;
    const float* cr = c + (b*128+ls)*80;
    const float* wr = w + t*80*64 + o;
    #pragma unroll 8
    for (int i=0;i<80;i++) acc += cr[i]*wr[i*64];
  }
  g_cc[(b*128+l)*64+o] = leaky(acc);
}

// ================= cond residual conv (k=3, 64->64) =================
__global__ void k_cond_res(int src_sel, int dst_sel, int add,
                           const float* __restrict__ w, const float* __restrict__ bias){
  const float* src = src_sel ? g_tmp : g_cc;
  float*       dst = dst_sel ? g_tmp : g_cc;
  int b = blockIdx.y, l = blockIdx.x, o = threadIdx.x;
  float acc = bias[o];
  #pragma unroll
  for (int t=0;t<3;t++){
    int ls = l-1+t;
    if (ls<0||ls>=128) continue;
    const float* sr = src + (b*128+ls)*64;
    const float* wr = w + t*64*64 + o;
    #pragma unroll 8
    for (int i=0;i<64;i++) acc += sr[i]*wr[i*64];
  }
  float v = leaky(acc);
  if (add) v += g_cc[(b*128+l)*64+o];
  dst[(b*128+l)*64+o] = v;
}

// ================= conv_transpose (k=16, s=8, pad (11,11)) =================
// n = 8m+4+j (j=0..7): x[m]*w[7-j] + x[m+1]*w[15-j]; input pre-activated with leaky.
#define CT_SMEM ((2176 + 8192)*4)
__global__ void __launch_bounds__(256) k_convt(const float* __restrict__ x,
                                               const float* __restrict__ ctw,
                                               const float* __restrict__ ctb){
  extern __shared__ float sm[];
  float* lxS = sm;          // 33 rows x pitch 65
  float* wS  = sm + 2176;   // 16 taps x 8 i x 64 o (chunk)
  int b = blockIdx.y, m0 = blockIdx.x*32;
  int tid = threadIdx.x;
  const float* xb = x + (size_t)b*4096*64;
  #pragma unroll 1
  for (int idx=tid; idx<33*64; idx+=256){
    int rr=idx>>6, i=idx&63; int m=m0+rr;
    lxS[rr*65+i] = (m<4096) ? leaky(xb[(size_t)m*64+i]) : 0.f;
  }
  int ts=tid&31, to=tid>>5;
  float acc[4][8][2];
  #pragma unroll
  for (int mm=0;mm<4;mm++)
    #pragma unroll
    for (int j=0;j<8;j++){ acc[mm][j][0]=0.f; acc[mm][j][1]=0.f; }

  for (int ch=0; ch<8; ch++){
    __syncthreads();
    #pragma unroll 1
    for (int idx=tid; idx<8192; idx+=256){
      int tap = idx>>9; int rem = idx&511; int ii=rem>>6; int o=rem&63;
      wS[idx] = ctw[(size_t)tap*4096 + (ch*8+ii)*64 + o];
    }
    __syncthreads();
    #pragma unroll
    for (int ii=0;ii<8;ii++){
      float lx[5];
      #pragma unroll
      for (int r=0;r<5;r++) lx[r] = lxS[(to*4+r)*65 + (ch*8+ii)];
      #pragma unroll
      for (int tap=0;tap<8;tap++){
        float2 w = *(const float2*)(wS + tap*512 + ii*64 + 2*ts);
        int j = 7-tap;
        #pragma unroll
        for (int mm=0;mm<4;mm++){
          acc[mm][j][0] += lx[mm]*w.x;
          acc[mm][j][1] += lx[mm]*w.y;
        }
      }
      #pragma unroll
      for (int tap=8;tap<16;tap++){
        float2 w = *(const float2*)(wS + tap*512 + ii*64 + 2*ts);
        int j = 15-tap;
        #pragma unroll
        for (int mm=0;mm<4;mm++){
          acc[mm][j][0] += lx[mm+1]*w.x;
          acc[mm][j][1] += lx[mm+1]*w.y;
        }
      }
    }
  }
  float c0 = ctb[2*ts], c1 = ctb[2*ts+1];
  float* hb = g_h[0] + (size_t)b*32768*64;
  #pragma unroll
  for (int mm=0;mm<4;mm++)
    #pragma unroll
    for (int j=0;j<8;j++){
      int n = 8*(m0+to*4+mm)+4+j;
      if (n < 32768){
        float2 v; v.x = acc[mm][j][0]+c0; v.y = acc[mm][j][1]+c1;
        *(float2*)(hb + (size_t)n*64 + 2*ts) = v;
      }
    }
}

// n = 0..3: single tap 11-n from x[0]
__global__ void k_convt_edge(const float* __restrict__ x, const float* __restrict__ ctw,
                             const float* __restrict__ ctb){
  int b = blockIdx.x; int n = threadIdx.x>>6, o = threadIdx.x&63;
  const float* xb = x + (size_t)b*4096*64;
  float acc = ctb[o];
  int tap = 11-n;
  #pragma unroll 8
  for (int i=0;i<64;i++) acc += leaky(xb[i]) * ctw[(size_t)tap*4096 + i*64 + o];
  g_h[0][((size_t)b*32768+n)*64+o] = acc;
}

// ========= kernel-predictor GEMM: [512 x 98304] = V[512x192] * W[192x98304] + b =========
#define GEMM_SMEM ((12288 + 2048)*4)
__global__ void __launch_bounds__(256) k_gemm(const float* __restrict__ W,
                                              const float* __restrict__ wb){
  extern __shared__ float smg[];
  float* As = smg;          // [k=192][m=64]
  float* Bs = smg + 12288;  // 2 x [8][128]
  int tid = threadIdx.x;
  int n0 = blockIdx.x*128, m0 = blockIdx.y*64;
  #pragma unroll 1
  for (int it=0; it<48; it++){
    int idx = tid + it*256;
    int k = idx>>6, mm_ = idx&63;
    int mg = m0+mm_; int b2 = mg>>7, l = mg&127;
    int t = k>>6, ic = k&63, ls = l-1+t;
    As[idx] = (ls>=0 && ls<128) ? g_cc[((b2<<7)+ls)*64+ic] : 0.f;
  }
  int brow = tid>>5, bcol = (tid&31)*4;
  *(float4*)(Bs + brow*128 + bcol) = *(const float4*)(W + (size_t)brow*98304 + n0 + bcol);
  __syncthreads();
  int tn = tid&15, tm = tid>>4;
  float acc[4][8];
  #pragma unroll
  for (int r=0;r<4;r++)
    #pragma unroll
    for (int q=0;q<8;q++) acc[r][q]=0.f;
  for (int kc=0; kc<24; kc++){
    float4 nb;
    if (kc<23) nb = *(const float4*)(W + (size_t)((kc+1)*8+brow)*98304 + n0 + bcol);
    const float* Bc = Bs + (kc&1)*1024;
    #pragma unroll
    for (int kk=0; kk<8; kk++){
      int k = kc*8+kk;
      float4 a  = *(const float4*)(As + k*64 + tm*4);
      float4 bA = *(const float4*)(Bc + kk*128 + tn*4);
      float4 bB = *(const float4*)(Bc + kk*128 + 64 + tn*4);
      float av[4] = {a.x,a.y,a.z,a.w};
      float bv[8] = {bA.x,bA.y,bA.z,bA.w,bB.x,bB.y,bB.z,bB.w};
      #pragma unroll
      for (int r=0;r<4;r++)
        #pragma unroll
        for (int q=0;q<8;q++) acc[r][q] += av[r]*bv[q];
    }
    __syncthreads();
    if (kc<23) *(float4*)(Bs + ((kc+1)&1)*1024 + brow*128 + bcol) = nb;
    __syncthreads();
  }
  int c1 = n0 + tn*4, c2 = n0 + 64 + tn*4;
  float bb0[8];
  #pragma unroll
  for (int q=0;q<4;q++){ bb0[q] = wb[c1+q]; bb0[q+4] = wb[c2+q]; }
  #pragma unroll
  for (int r=0;r<4;r++){
    size_t row = (size_t)(m0 + tm*4 + r)*98304;
    float4 v1, v2;
    v1.x=acc[r][0]+bb0[0]; v1.y=acc[r][1]+bb0[1]; v1.z=acc[r][2]+bb0[2]; v1.w=acc[r][3]+bb0[3];
    v2.x=acc[r][4]+bb0[4]; v2.y=acc[r][5]+bb0[5]; v2.z=acc[r][6]+bb0[6]; v2.w=acc[r][7]+bb0[7];
    *(float4*)(g_k + row + c1) = v1;
    *(float4*)(g_k + row + c2) = v2;
  }
}

// ================= bias-predictor GEMM: [512 x 512] =================
__global__ void k_gemm_b(const float* __restrict__ W, const float* __restrict__ wb){
  int mrow = blockIdx.x;              // b*128 + l
  int b = mrow>>7, l = mrow&127;
  int n = threadIdx.x*4;
  float4 acc; acc.x=wb[n]; acc.y=wb[n+1]; acc.z=wb[n+2]; acc.w=wb[n+3];
  #pragma unroll
  for (int t=0;t<3;t++){
    int ls = l-1+t; if (ls<0||ls>=128) continue;
    const float* cr = g_cc + ((b<<7)+ls)*64;
    #pragma unroll 4
    for (int i=0;i<64;i++){
      float v = cr[i];
      float4 wv = *(const float4*)(W + (size_t)(t*64+i)*512 + n);
      acc.x += v*wv.x; acc.y += v*wv.y; acc.z += v*wv.z; acc.w += v*wv.w;
    }
  }
  *(float4*)(g_bb + mrow*512 + n) = acc;
}

// ================= dilated conv (k=3, 64->64), input leaky(h) =================
#define DC_SMEM ((12288 + (64+2*27)*65 + 16)*4)
__global__ void __launch_bounds__(256) k_dilconv(int layer, int parity, int d,
                                                 const float* __restrict__ cw,
                                                 const float* __restrict__ cb){
  extern __shared__ float sm[];
  float* wS = sm;            // [t][i][o] 12288
  float* hS = sm + 12288;    // (64+2d) rows x pitch 65
  int b = blockIdx.y, n0 = blockIdx.x*64;
  int tid = threadIdx.x;
  const float* hb = g_h[parity] + (size_t)b*32768*64;
  const float* cwl = cw + (size_t)layer*3*64*64;
  #pragma unroll 1
  for (int idx=tid; idx<12288; idx+=256) wS[idx] = cwl[idx];
  int nrows = 64 + 2*d;
  #pragma unroll 1
  for (int idx=tid; idx<nrows*64; idx+=256){
    int rr=idx>>6, i=idx&63;
    int g = n0 - d + rr;
    hS[rr*65+i] = (g>=0 && g<32768) ? leaky(hb[(size_t)g*64+i]) : 0.f;
  }
  __syncthreads();
  int ts=tid&31, to=tid>>5;
  float a0[8], a1[8];
  #pragma unroll
  for (int mm=0;mm<8;mm++){ a0[mm]=0.f; a1[mm]=0.f; }
  for (int i=0;i<64;i++){
    #pragma unroll
    for (int t=0;t<3;t++){
      float2 w = *(const float2*)(wS + t*4096 + i*64 + 2*ts);
      #pragma unroll
      for (int mm=0;mm<8;mm++){
        float a = hS[(to*8+mm+t*d)*65 + i];
        a0[mm] += a*w.x; a1[mm] += a*w.y;
      }
    }
  }
  float c0 = cb[layer*64 + 2*ts], c1 = cb[layer*64 + 2*ts + 1];
  #pragma unroll
  for (int mm=0;mm<8;mm++){
    int n = n0 + to*8 + mm;
    float2 v; v.x = leaky(a0[mm]+c0); v.y = leaky(a1[mm]+c1);
    *(float2*)(g_o1 + ((size_t)b*32768 + n)*64 + 2*ts) = v;
  }
}

// ================= LVC + gated residual, one block per (b, segment L) =================
#define LVC_SMEM ((16960 + 24576 + 128)*4)
__global__ void __launch_bounds__(256,1) k_lvc(int layer, int parity, int is_last,
                                               float* __restrict__ dout){
  extern __shared__ float sm[];
  float* seg = sm;                 // [i=64][pitch 265], m in [0,258)
  float* Ws  = sm + 16960;         // [k=192][o=128]
  float* bS  = sm + 16960 + 24576; // [128]
  int b = blockIdx.y, L = blockIdx.x;
  int tid = threadIdx.x;

  const float* o1b = g_o1 + (size_t)b*32768*64;
  int t0 = L*256 - 1;
  #pragma unroll 1
  for (int idx=tid; idx<258*64; idx+=256){
    int m = idx>>6, i = idx&63;
    int t = t0 + m;
    seg[i*265 + m] = (t>=0 && t<32768) ? o1b[(size_t)t*64 + i] : 0.f;
  }
  int la = layer*128 + L;
  int l = la>>2, q = la&3;
  const float* kb = g_k + (size_t)(b*128+l)*98304 + q*24576;
  #pragma unroll 1
  for (int idx=tid; idx<24576; idx+=256){
    int i = idx/384; int rem = idx - i*384; int o = rem/3; int kk = rem - o*3;
    Ws[(i*3+kk)*128 + o] = kb[idx];
  }
  if (tid < 128) bS[tid] = g_bb[(b*128+l)*512 + q*128 + tid];
  __syncthreads();

  int ts = tid&31, to = tid>>5;
  const float* hin = g_h[parity];
  float* hout = is_last ? dout : g_h[parity^1];
  size_t nbase = (size_t)b*32768 + (size_t)L*256;
  float b0 = bS[ts], b1 = bS[ts+64], b2 = bS[ts+32], b3 = bS[ts+96];

  for (int ph=0; ph<4; ph++){
    int sbase = to*32 + ph*8;
    int mmidx[8][3];
    #pragma unroll
    for (int ss=0;ss<8;ss++)
      #pragma unroll
      for (int kk=0;kk<3;kk++){
        int pos = 3*(sbase+ss) + kk - 255;
        if (pos < 0) pos = -pos;
        else if (pos > 257) pos = 514 - pos;
        mmidx[ss][kk] = pos;
      }
    float ac0[8], ac1[8], ac2[8], ac3[8];
    #pragma unroll
    for (int ss=0;ss<8;ss++){ ac0[ss]=0.f; ac1[ss]=0.f; ac2[ss]=0.f; ac3[ss]=0.f; }
    for (int i=0;i<64;i++){
      const float* segr = seg + i*265;
      #pragma unroll
      for (int kk=0;kk<3;kk++){
        const float* wr = Ws + (i*3+kk)*128;
        float w0 = wr[ts], w1 = wr[ts+64], w2 = wr[ts+32], w3 = wr[ts+96];
        #pragma unroll
        for (int ss=0;ss<8;ss++){
          float a = segr[mmidx[ss][kk]];
          ac0[ss] += a*w0; ac1[ss] += a*w1; ac2[ss] += a*w2; ac3[ss] += a*w3;
        }
      }
    }
    #pragma unroll
    for (int ss=0;ss<8;ss++){
      size_t gi = (nbase + sbase + ss)*64;
      float s0 = ac0[ss]+b0, t1 = ac1[ss]+b1;
      float g0 = (1.f/(1.f+__expf(-s0))) * tanhf(t1);
      hout[gi+ts] = hin[gi+ts] + g0;
      float s2 = ac2[ss]+b2, t3 = ac3[ss]+b3;
      float g1 = (1.f/(1.f+__expf(-s2))) * tanhf(t3);
      hout[gi+ts+32] = hin[gi+ts+32] + g1;
    }
  }
}

// ================= launch =================
extern "C" void kernel_launch(void* const* d_in, const int* in_sizes, int n_in,
                              void* d_out, int out_size){
  const float* x      = (const float*)d_in[0];
  const float* c      = (const float*)d_in[1];
  const float* ct_w   = (const float*)d_in[2];
  const float* ct_b   = (const float*)d_in[3];
  const float* conv_w = (const float*)d_in[4];
  const float* conv_b = (const float*)d_in[5];
  const float* inp_w  = (const float*)d_in[6];
  const float* inp_b  = (const float*)d_in[7];
  const float* res_w1 = (const float*)d_in[8];
  const float* res_b1 = (const float*)d_in[9];
  const float* res_w2 = (const float*)d_in[10];
  const float* res_b2 = (const float*)d_in[11];
  const float* kern_w = (const float*)d_in[12];
  const float* kern_b = (const float*)d_in[13];
  const float* bias_w = (const float*)d_in[14];
  const float* bias_b = (const float*)d_in[15];
  float* out = (float*)d_out;

  cudaFuncSetAttribute(k_gemm,    cudaFuncAttributeMaxDynamicSharedMemorySize, GEMM_SMEM);
  cudaFuncSetAttribute(k_dilconv, cudaFuncAttributeMaxDynamicSharedMemorySize, DC_SMEM);
  cudaFuncSetAttribute(k_lvc,     cudaFuncAttributeMaxDynamicSharedMemorySize, LVC_SMEM);
  cudaFuncSetAttribute(k_convt,   cudaFuncAttributeMaxDynamicSharedMemorySize, CT_SMEM);

  // conv_transpose -> g_h[0]
  k_convt<<<dim3(128,4), 256, CT_SMEM>>>(x, ct_w, ct_b);
  k_convt_edge<<<4, 256>>>(x, ct_w, ct_b);

  // cond net -> g_cc
  k_cond_in<<<dim3(128,4), 64>>>(c, inp_w, inp_b);
  for (int j=0;j<3;j++){
    k_cond_res<<<dim3(128,4), 64>>>(0, 1, 0, res_w1 + (size_t)j*3*64*64, res_b1 + j*64);
    k_cond_res<<<dim3(128,4), 64>>>(1, 0, 1, res_w2 + (size_t)j*3*64*64, res_b2 + j*64);
  }

  // predictors
  k_gemm_b<<<512, 128>>>(bias_w, bias_b);
  k_gemm<<<dim3(768,8), 256, GEMM_SMEM>>>(kern_w, kern_b);

  // 4 LVC layers
  const int dil1=1, dil2=3, dil3=9, dil4=27;
  const int dil[4] = {dil1,dil2,dil3,dil4};
  for (int a=0;a<4;a++){
    int parity = a & 1;
    k_dilconv<<<dim3(512,4), 256, DC_SMEM>>>(a, parity, dil[a], conv_w, conv_b);
    k_lvc<<<dim3(128,4), 256, LVC_SMEM>>>(a, parity, (a==3)?1:0, out);
  }
  (void)in_sizes; (void)n_in; (void)out_size;
}

// round 5
// speedup vs baseline: 1.1231x; 1.1231x over previous
#include <cuda_runtime.h>
#include <math.h>

#define DEVINL __device__ __forceinline__

static DEVINL float leaky(float v){ return v > 0.f ? v : 0.2f*v; }

// ---------------- persistent scratch (no runtime allocation) ----------------
__device__ float g_cc [4*128*64];
__device__ float g_bb [512*512];
__device__ float g_k  [512*98304];            // 201 MB kernel-predictor output
__device__ float g_h  [2][4*32768*64];        // ping-pong h
__device__ float g_o1 [4*32768*64];           // dilated-conv output

// ================= fused cond net: input conv (k=5,80->64) + 3 residual blocks =================
// grid (8,4): 16 output positions per block, halo-redundant compute (rows r in [-6,22)).
#define COND_SMEM ((32*80 + 28*64 + 28*64 + 12288)*4)
__global__ void __launch_bounds__(256) k_cond_fused(
    const float* __restrict__ c,
    const float* __restrict__ inp_w, const float* __restrict__ inp_b,
    const float* __restrict__ res_w1, const float* __restrict__ res_b1,
    const float* __restrict__ res_w2, const float* __restrict__ res_b2){
  extern __shared__ float sm[];
  float* sC = sm;                    // 32 rows x 80
  float* sA = sm + 32*80;            // cc: 28 rows x 64 (row ri = r+6)
  float* sB = sA + 28*64;            // t : 28 rows x 64
  float* sW = sB + 28*64;            // 12288
  int b = blockIdx.y, p0 = blockIdx.x*16;
  int tid = threadIdx.x;
  int o = tid & 63, q = tid >> 6;    // q in [0,4)

  // stage c input: rows g = p0-8+cr, cr in [0,32)
  #pragma unroll 1
  for (int idx=tid; idx<32*80; idx+=256){
    int cr = idx/80, ch = idx - cr*80;
    int g = p0 - 8 + cr;
    sC[idx] = (g>=0 && g<128) ? c[((size_t)b*128+g)*80 + ch] : 0.f;
  }
  __syncthreads();

  // stage0: conv k=5, 80->64, leaky. rows r = -6..21
  {
    float acc[7];
    #pragma unroll
    for (int k=0;k<7;k++) acc[k] = inp_b[o];
    #pragma unroll 1
    for (int t=0;t<5;t++){
      #pragma unroll 1
      for (int i=0;i<80;i++){
        float w = inp_w[(t*80+i)*64 + o];
        #pragma unroll
        for (int k=0;k<7;k++){
          int r = -6 + q*7 + k;
          acc[k] += sC[(r+t+6)*80 + i] * w;
        }
      }
    }
    #pragma unroll
    for (int k=0;k<7;k++){
      int r = -6 + q*7 + k;
      int g = p0 + r;
      sA[(r+6)*64 + o] = (g>=0 && g<128) ? leaky(acc[k]) : 0.f;
    }
  }

  // 6 residual conv stages
  #pragma unroll 1
  for (int s=0; s<6; s++){
    int j = s>>1, half = s&1;
    const float* w  = half ? (res_w2 + (size_t)j*3*64*64) : (res_w1 + (size_t)j*3*64*64);
    const float* bi = half ? (res_b2 + j*64) : (res_b1 + j*64);
    __syncthreads();
    #pragma unroll 1
    for (int idx=tid; idx<12288; idx+=256) sW[idx] = w[idx];
    __syncthreads();
    const float* src = half ? sB : sA;
    int lo = s-5, hi = 21-s;   // rows [lo, hi)
    float acc[7];
    int rr[7];
    #pragma unroll
    for (int k=0;k<7;k++){ acc[k] = bi[o]; rr[k] = lo + q*7 + k; }
    #pragma unroll 1
    for (int t=0;t<3;t++){
      #pragma unroll 1
      for (int i=0;i<64;i++){
        float wv = sW[(t*64+i)*64 + o];
        #pragma unroll
        for (int k=0;k<7;k++){
          int r = rr[k];
          if (r < hi) acc[k] += src[(r+t+5)*64 + i] * wv;
        }
      }
    }
    #pragma unroll
    for (int k=0;k<7;k++){
      int r = rr[k];
      if (r < hi){
        int g = p0 + r;
        if (half){
          if (g>=0 && g<128) sA[(r+6)*64+o] += leaky(acc[k]);
        } else {
          sB[(r+6)*64+o] = (g>=0 && g<128) ? leaky(acc[k]) : 0.f;
        }
      }
    }
  }
  __syncthreads();

  // write back rows [0,16)
  #pragma unroll 1
  for (int idx=tid; idx<16*64; idx+=256){
    int r = idx>>6, oo = idx&63;
    g_cc[((size_t)b*128 + p0 + r)*64 + oo] = sA[(r+6)*64 + oo];
  }
}

// ================= conv_transpose (k=16, s=8, pad (11,11)) =================
#define CT_SMEM ((2176 + 8192)*4)
__global__ void __launch_bounds__(256) k_convt(const float* __restrict__ x,
                                               const float* __restrict__ ctw,
                                               const float* __restrict__ ctb){
  extern __shared__ float sm[];
  float* lxS = sm;          // 33 rows x pitch 65
  float* wS  = sm + 2176;   // 16 taps x 8 i x 64 o (chunk)
  int b = blockIdx.y, m0 = blockIdx.x*32;
  int tid = threadIdx.x;
  const float* xb = x + (size_t)b*4096*64;
  #pragma unroll 1
  for (int idx=tid; idx<33*64; idx+=256){
    int rr=idx>>6, i=idx&63; int m=m0+rr;
    lxS[rr*65+i] = (m<4096) ? leaky(xb[(size_t)m*64+i]) : 0.f;
  }
  int ts=tid&31, to=tid>>5;
  float acc[4][8][2];
  #pragma unroll
  for (int mm=0;mm<4;mm++)
    #pragma unroll
    for (int j=0;j<8;j++){ acc[mm][j][0]=0.f; acc[mm][j][1]=0.f; }

  for (int ch=0; ch<8; ch++){
    __syncthreads();
    #pragma unroll 1
    for (int idx=tid; idx<8192; idx+=256){
      int tap = idx>>9; int rem = idx&511; int ii=rem>>6; int o=rem&63;
      wS[idx] = ctw[(size_t)tap*4096 + (ch*8+ii)*64 + o];
    }
    __syncthreads();
    #pragma unroll
    for (int ii=0;ii<8;ii++){
      float lx[5];
      #pragma unroll
      for (int r=0;r<5;r++) lx[r] = lxS[(to*4+r)*65 + (ch*8+ii)];
      #pragma unroll
      for (int tap=0;tap<8;tap++){
        float2 w = *(const float2*)(wS + tap*512 + ii*64 + 2*ts);
        int j = 7-tap;
        #pragma unroll
        for (int mm=0;mm<4;mm++){
          acc[mm][j][0] += lx[mm]*w.x;
          acc[mm][j][1] += lx[mm]*w.y;
        }
      }
      #pragma unroll
      for (int tap=8;tap<16;tap++){
        float2 w = *(const float2*)(wS + tap*512 + ii*64 + 2*ts);
        int j = 15-tap;
        #pragma unroll
        for (int mm=0;mm<4;mm++){
          acc[mm][j][0] += lx[mm+1]*w.x;
          acc[mm][j][1] += lx[mm+1]*w.y;
        }
      }
    }
  }
  float c0 = ctb[2*ts], c1 = ctb[2*ts+1];
  float* hb = g_h[0] + (size_t)b*32768*64;
  #pragma unroll
  for (int mm=0;mm<4;mm++)
    #pragma unroll
    for (int j=0;j<8;j++){
      int n = 8*(m0+to*4+mm)+4+j;
      if (n < 32768){
        float2 v; v.x = acc[mm][j][0]+c0; v.y = acc[mm][j][1]+c1;
        *(float2*)(hb + (size_t)n*64 + 2*ts) = v;
      }
    }
}

// n = 0..3: single tap 11-n from x[0]
__global__ void k_convt_edge(const float* __restrict__ x, const float* __restrict__ ctw,
                             const float* __restrict__ ctb){
  int b = blockIdx.x; int n = threadIdx.x>>6, o = threadIdx.x&63;
  const float* xb = x + (size_t)b*4096*64;
  float acc = ctb[o];
  int tap = 11-n;
  #pragma unroll 8
  for (int i=0;i<64;i++) acc += leaky(xb[i]) * ctw[(size_t)tap*4096 + i*64 + o];
  g_h[0][((size_t)b*32768+n)*64+o] = acc;
}

// ========= kernel-predictor GEMM: [512 x 98304] = V[512x192] * W[192x98304] + b =========
#define GEMM_SMEM ((12288 + 2048)*4)
__global__ void __launch_bounds__(256) k_gemm(const float* __restrict__ W,
                                              const float* __restrict__ wb){
  extern __shared__ float smg[];
  float* As = smg;          // [k=192][m=64]
  float* Bs = smg + 12288;  // 2 x [8][128]
  int tid = threadIdx.x;
  int n0 = blockIdx.x*128, m0 = blockIdx.y*64;
  #pragma unroll 1
  for (int it=0; it<48; it++){
    int idx = tid + it*256;
    int k = idx>>6, mm_ = idx&63;
    int mg = m0+mm_; int b2 = mg>>7, l = mg&127;
    int t = k>>6, ic = k&63, ls = l-1+t;
    As[idx] = (ls>=0 && ls<128) ? g_cc[((b2<<7)+ls)*64+ic] : 0.f;
  }
  int brow = tid>>5, bcol = (tid&31)*4;
  *(float4*)(Bs + brow*128 + bcol) = *(const float4*)(W + (size_t)brow*98304 + n0 + bcol);
  __syncthreads();
  int tn = tid&15, tm = tid>>4;
  float acc[4][8];
  #pragma unroll
  for (int r=0;r<4;r++)
    #pragma unroll
    for (int q=0;q<8;q++) acc[r][q]=0.f;
  for (int kc=0; kc<24; kc++){
    float4 nb;
    if (kc<23) nb = *(const float4*)(W + (size_t)((kc+1)*8+brow)*98304 + n0 + bcol);
    const float* Bc = Bs + (kc&1)*1024;
    #pragma unroll
    for (int kk=0; kk<8; kk++){
      int k = kc*8+kk;
      float4 a  = *(const float4*)(As + k*64 + tm*4);
      float4 bA = *(const float4*)(Bc + kk*128 + tn*4);
      float4 bB = *(const float4*)(Bc + kk*128 + 64 + tn*4);
      float av[4] = {a.x,a.y,a.z,a.w};
      float bv[8] = {bA.x,bA.y,bA.z,bA.w,bB.x,bB.y,bB.z,bB.w};
      #pragma unroll
      for (int r=0;r<4;r++)
        #pragma unroll
        for (int q=0;q<8;q++) acc[r][q] += av[r]*bv[q];
    }
    __syncthreads();
    if (kc<23) *(float4*)(Bs + ((kc+1)&1)*1024 + brow*128 + bcol) = nb;
    __syncthreads();
  }
  int c1 = n0 + tn*4, c2 = n0 + 64 + tn*4;
  float bb0[8];
  #pragma unroll
  for (int q=0;q<4;q++){ bb0[q] = wb[c1+q]; bb0[q+4] = wb[c2+q]; }
  #pragma unroll
  for (int r=0;r<4;r++){
    size_t row = (size_t)(m0 + tm*4 + r)*98304;
    float4 v1, v2;
    v1.x=acc[r][0]+bb0[0]; v1.y=acc[r][1]+bb0[1]; v1.z=acc[r][2]+bb0[2]; v1.w=acc[r][3]+bb0[3];
    v2.x=acc[r][4]+bb0[4]; v2.y=acc[r][5]+bb0[5]; v2.z=acc[r][6]+bb0[6]; v2.w=acc[r][7]+bb0[7];
    *(float4*)(g_k + row + c1) = v1;
    *(float4*)(g_k + row + c2) = v2;
  }
}

// ================= bias-predictor GEMM: [512 x 512] =================
__global__ void k_gemm_b(const float* __restrict__ W, const float* __restrict__ wb){
  int mrow = blockIdx.x;              // b*128 + l
  int b = mrow>>7, l = mrow&127;
  int n = threadIdx.x*4;
  float4 acc; acc.x=wb[n]; acc.y=wb[n+1]; acc.z=wb[n+2]; acc.w=wb[n+3];
  #pragma unroll
  for (int t=0;t<3;t++){
    int ls = l-1+t; if (ls<0||ls>=128) continue;
    const float* cr = g_cc + ((b<<7)+ls)*64;
    #pragma unroll 4
    for (int i=0;i<64;i++){
      float v = cr[i];
      float4 wv = *(const float4*)(W + (size_t)(t*64+i)*512 + n);
      acc.x += v*wv.x; acc.y += v*wv.y; acc.z += v*wv.z; acc.w += v*wv.w;
    }
  }
  *(float4*)(g_bb + mrow*512 + n) = acc;
}

// ================= dilated conv (k=3, 64->64), input leaky(h) =================
#define DC_SMEM ((12288 + (64+2*27)*65 + 16)*4)
__global__ void __launch_bounds__(256) k_dilconv(int layer, int parity, int d,
                                                 const float* __restrict__ cw,
                                                 const float* __restrict__ cb){
  extern __shared__ float sm[];
  float* wS = sm;            // [t][i][o] 12288
  float* hS = sm + 12288;    // (64+2d) rows x pitch 65
  int b = blockIdx.y, n0 = blockIdx.x*64;
  int tid = threadIdx.x;
  const float* hb = g_h[parity] + (size_t)b*32768*64;
  const float* cwl = cw + (size_t)layer*3*64*64;
  #pragma unroll 1
  for (int idx=tid; idx<12288; idx+=256) wS[idx] = cwl[idx];
  int nrows = 64 + 2*d;
  #pragma unroll 1
  for (int idx=tid; idx<nrows*64; idx+=256){
    int rr=idx>>6, i=idx&63;
    int g = n0 - d + rr;
    hS[rr*65+i] = (g>=0 && g<32768) ? leaky(hb[(size_t)g*64+i]) : 0.f;
  }
  __syncthreads();
  int ts=tid&31, to=tid>>5;
  float a0[8], a1[8];
  #pragma unroll
  for (int mm=0;mm<8;mm++){ a0[mm]=0.f; a1[mm]=0.f; }
  for (int i=0;i<64;i++){
    #pragma unroll
    for (int t=0;t<3;t++){
      float2 w = *(const float2*)(wS + t*4096 + i*64 + 2*ts);
      #pragma unroll
      for (int mm=0;mm<8;mm++){
        float a = hS[(to*8+mm+t*d)*65 + i];
        a0[mm] += a*w.x; a1[mm] += a*w.y;
      }
    }
  }
  float c0 = cb[layer*64 + 2*ts], c1 = cb[layer*64 + 2*ts + 1];
  #pragma unroll
  for (int mm=0;mm<8;mm++){
    int n = n0 + to*8 + mm;
    float2 v; v.x = leaky(a0[mm]+c0); v.y = leaky(a1[mm]+c1);
    *(float2*)(g_o1 + ((size_t)b*32768 + n)*64 + 2*ts) = v;
  }
}

// ================= LVC + gated residual, one block per (b, segment L), 512 threads =========
#define LVC_SMEM ((16960 + 24576 + 128)*4)
__global__ void __launch_bounds__(512,1) k_lvc(int layer, int parity, int is_last,
                                               float* __restrict__ dout){
  extern __shared__ float sm[];
  float* seg = sm;                 // [i=64][pitch 265], m in [0,258)
  float* Ws  = sm + 16960;         // [k=192][o=128]
  float* bS  = sm + 16960 + 24576; // [128]
  int b = blockIdx.y, L = blockIdx.x;
  int tid = threadIdx.x;

  const float* o1b = g_o1 + (size_t)b*32768*64;
  int t0 = L*256 - 1;
  #pragma unroll 1
  for (int idx=tid; idx<258*64; idx+=512){
    int m = idx>>6, i = idx&63;
    int t = t0 + m;
    seg[i*265 + m] = (t>=0 && t<32768) ? o1b[(size_t)t*64 + i] : 0.f;
  }
  int la = layer*128 + L;
  int l = la>>2, q = la&3;
  const float* kb = g_k + (size_t)(b*128+l)*98304 + q*24576;
  #pragma unroll 1
  for (int idx=tid; idx<24576; idx+=512){
    int i = idx/384; int rem = idx - i*384; int o = rem/3; int kk = rem - o*3;
    Ws[(i*3+kk)*128 + o] = kb[idx];
  }
  if (tid < 128) bS[tid] = g_bb[(b*128+l)*512 + q*128 + tid];
  __syncthreads();

  int ts = tid&31, to = tid>>5;   // to in [0,16)
  const float* hin = g_h[parity];
  float* hout = is_last ? dout : g_h[parity^1];
  size_t nbase = (size_t)b*32768 + (size_t)L*256;
  float b0 = bS[ts], b1 = bS[ts+64], b2 = bS[ts+32], b3 = bS[ts+96];

  #pragma unroll 1
  for (int ph=0; ph<2; ph++){
    int sbase = to*16 + ph*8;
    int mmidx[8][3];
    #pragma unroll
    for (int ss=0;ss<8;ss++)
      #pragma unroll
      for (int kk=0;kk<3;kk++){
        int pos = 3*(sbase+ss) + kk - 255;
        if (pos < 0) pos = -pos;
        else if (pos > 257) pos = 514 - pos;
        mmidx[ss][kk] = pos;
      }
    float ac0[8], ac1[8], ac2[8], ac3[8];
    #pragma unroll
    for (int ss=0;ss<8;ss++){ ac0[ss]=0.f; ac1[ss]=0.f; ac2[ss]=0.f; ac3[ss]=0.f; }
    for (int i=0;i<64;i++){
      const float* segr = seg + i*265;
      #pragma unroll
      for (int kk=0;kk<3;kk++){
        const float* wr = Ws + (i*3+kk)*128;
        float w0 = wr[ts], w1 = wr[ts+64], w2 = wr[ts+32], w3 = wr[ts+96];
        #pragma unroll
        for (int ss=0;ss<8;ss++){
          float a = segr[mmidx[ss][kk]];
          ac0[ss] += a*w0; ac1[ss] += a*w1; ac2[ss] += a*w2; ac3[ss] += a*w3;
        }
      }
    }
    #pragma unroll
    for (int ss=0;ss<8;ss++){
      size_t gi = (nbase + sbase + ss)*64;
      float s0 = ac0[ss]+b0, t1 = ac1[ss]+b1;
      float g0 = (1.f/(1.f+__expf(-s0))) * tanhf(t1);
      hout[gi+ts] = hin[gi+ts] + g0;
      float s2 = ac2[ss]+b2, t3 = ac3[ss]+b3;
      float g1 = (1.f/(1.f+__expf(-s2))) * tanhf(t3);
      hout[gi+ts+32] = hin[gi+ts+32] + g1;
    }
  }
}

// ================= launch =================
extern "C" void kernel_launch(void* const* d_in, const int* in_sizes, int n_in,
                              void* d_out, int out_size){
  const float* x      = (const float*)d_in[0];
  const float* c      = (const float*)d_in[1];
  const float* ct_w   = (const float*)d_in[2];
  const float* ct_b   = (const float*)d_in[3];
  const float* conv_w = (const float*)d_in[4];
  const float* conv_b = (const float*)d_in[5];
  const float* inp_w  = (const float*)d_in[6];
  const float* inp_b  = (const float*)d_in[7];
  const float* res_w1 = (const float*)d_in[8];
  const float* res_b1 = (const float*)d_in[9];
  const float* res_w2 = (const float*)d_in[10];
  const float* res_b2 = (const float*)d_in[11];
  const float* kern_w = (const float*)d_in[12];
  const float* kern_b = (const float*)d_in[13];
  const float* bias_w = (const float*)d_in[14];
  const float* bias_b = (const float*)d_in[15];
  float* out = (float*)d_out;

  cudaFuncSetAttribute(k_cond_fused, cudaFuncAttributeMaxDynamicSharedMemorySize, COND_SMEM);
  cudaFuncSetAttribute(k_gemm,    cudaFuncAttributeMaxDynamicSharedMemorySize, GEMM_SMEM);
  cudaFuncSetAttribute(k_dilconv, cudaFuncAttributeMaxDynamicSharedMemorySize, DC_SMEM);
  cudaFuncSetAttribute(k_lvc,     cudaFuncAttributeMaxDynamicSharedMemorySize, LVC_SMEM);
  cudaFuncSetAttribute(k_convt,   cudaFuncAttributeMaxDynamicSharedMemorySize, CT_SMEM);

  // 1: cond net -> g_cc
  k_cond_fused<<<dim3(8,4), 256, COND_SMEM>>>(c, inp_w, inp_b, res_w1, res_b1, res_w2, res_b2);
  // 2,3: conv_transpose -> g_h[0]
  k_convt<<<dim3(128,4), 256, CT_SMEM>>>(x, ct_w, ct_b);
  k_convt_edge<<<4, 256>>>(x, ct_w, ct_b);
  // 4: bias predictor
  k_gemm_b<<<512, 128>>>(bias_w, bias_b);
  // 5: dilated conv layer 0 (independent of gemm)
  k_dilconv<<<dim3(512,4), 256, DC_SMEM>>>(0, 0, 1, conv_w, conv_b);
  // 6: kernel predictor GEMM  (<- ncu captures this launch)
  k_gemm<<<dim3(768,8), 256, GEMM_SMEM>>>(kern_w, kern_b);
  // 7: LVC layer 0
  k_lvc<<<dim3(128,4), 512, LVC_SMEM>>>(0, 0, 0, out);

  const int dil[4] = {1,3,9,27};
  for (int a=1;a<4;a++){
    int parity = a & 1;
    k_dilconv<<<dim3(512,4), 256, DC_SMEM>>>(a, parity, dil[a], conv_w, conv_b);
    k_lvc<<<dim3(128,4), 512, LVC_SMEM>>>(a, parity, (a==3)?1:0, out);
  }
  (void)in_sizes; (void)n_in; (void)out_size;
}